// round 15
// baseline (speedup 1.0000x reference)
#include <cuda_runtime.h>
#include <cuda_fp16.h>
#include <math.h>
#include <stdint.h>

// ---------------- problem constants ----------------
#define NP 200000
#define NA 100000
#define NKW 50000
#define NN 350000
#define C 128
#define H 4
#define D 32
#define LAYERS 2
#define NR 4
#define E_TOT 600000
#define SRC_TOT 700000   // rel0: A(100k) srcs, rel1-3: P(200k) each

static const int OFFS_H[3]     = {0, NP, NP + NA};
static const int KRELOFF_H[4]  = {0, NA, NA + NP, NA + 2*NP};
static const int NT_H[3]       = {NP, NA, NKW};

// ---------------- scratch ----------------
__device__ __half g_X    [(size_t)NN * C];           // fp16 X (skip source)
__device__ __half g_Q    [(size_t)NN * C];           // fp16 Q
__device__ __half g_KV   [(size_t)SRC_TOT * 256];    // fp16 [Krel(128) | Vrel(128)]
__device__ float  g_denom[(size_t)NN * H];
__device__ __half g_agg  [(size_t)NN * C];           // fp16 unnormalized agg
__device__ unsigned char g_wimg[2031616];
__device__ float  g_bias[3968];
// CSR (built once)
__device__ int g_counts[NN];
__device__ int g_starts[NN];
__device__ int g_cursor[NN];
__device__ int g_bsums[512];
__device__ int g_boffs[512];
__device__ unsigned int g_eidx[E_TOT];

#define IMG_IN(t)     ((size_t)(t) * 65536)
#define IMG_Q(l,t)    ((size_t)(3 + (l)*3 + (t)) * 65536)
#define IMG_OUT(l,t)  ((size_t)(9 + (l)*3 + (t)) * 65536)
#define IMG_KV(l,r)   ((size_t)15 * 65536 + (size_t)((l)*4 + (r)) * 131072)
#define B_IN(t)     ((t) * 128)
#define B_Q(l,t)    (384 + ((l)*3 + (t)) * 128)
#define B_OUT(l,t)  (1152 + ((l)*3 + (t)) * 128)
#define B_KV(l,r)   (1920 + ((l)*4 + (r)) * 256)

// ---------------- helpers ----------------
__device__ __forceinline__ uint32_t smem_to_u32(const void* p) {
    uint32_t a;
    asm("{ .reg .u64 t; cvta.to.shared.u64 t, %1; cvt.u32.u64 %0, t; }" : "=r"(a) : "l"(p));
    return a;
}
__device__ __forceinline__ float gelu_f(float x) {
    return 0.5f * x * (1.0f + erff(x * 0.70710678118654752440f));
}
__device__ __forceinline__ void ldm_x4(uint32_t* r, uint32_t a) {
    asm volatile("ldmatrix.sync.aligned.m8n8.x4.shared.b16 {%0,%1,%2,%3}, [%4];"
                 : "=r"(r[0]), "=r"(r[1]), "=r"(r[2]), "=r"(r[3]) : "r"(a));
}
__device__ __forceinline__ void ldm_x4_t(uint32_t* r, uint32_t a) {
    asm volatile("ldmatrix.sync.aligned.m8n8.x4.trans.shared.b16 {%0,%1,%2,%3}, [%4];"
                 : "=r"(r[0]), "=r"(r[1]), "=r"(r[2]), "=r"(r[3]) : "r"(a));
}
__device__ __forceinline__ void mma_f16(float* d, const uint32_t* a, const uint32_t* b) {
    asm volatile(
        "mma.sync.aligned.m16n8k16.row.col.f32.f16.f16.f32 "
        "{%0,%1,%2,%3}, {%4,%5,%6,%7}, {%8,%9}, {%0,%1,%2,%3};"
        : "+f"(d[0]), "+f"(d[1]), "+f"(d[2]), "+f"(d[3])
        : "r"(a[0]), "r"(a[1]), "r"(a[2]), "r"(a[3]), "r"(b[0]), "r"(b[1]));
}
__device__ __forceinline__ void cp16(uint32_t dst, const void* src) {
    asm volatile("cp.async.cg.shared.global [%0], [%1], 16;" :: "r"(dst), "l"(src));
}

// ---------------- batched weight prep: fp32 -> fp16 image ----------------
struct PPlain { const float* W; long ldW; const float* bias; unsigned char* img; float* bOut; };
struct PPlainList { PPlain p[15]; };

__global__ void prep_plain_all(PPlainList L)
{
    const PPlain pp = L.p[blockIdx.y];
    int idx = blockIdx.x * blockDim.x + threadIdx.x;
    int n = idx & 127, k = idx >> 7;
    float v = pp.W[(size_t)k * pp.ldW + n];
    *(__half*)(pp.img + ((size_t)k * 128 + n) * 2) = __float2half_rn(v);
    if (k == 0) pp.bOut[n] = pp.bias[n];
}

struct PKV { const float* Wkqv; const float* bkqv; const float* Wk; const float* Wv;
             unsigned char* img; float* bOut; };
struct PKVList { PKV p[8]; };

__global__ void prep_kv_all(PKVList L)
{
    const PKV pp = L.p[blockIdx.y];
    int idx = blockIdx.x * blockDim.x + threadIdx.x;
    int n = idx & 255, k = idx >> 8;
    int isV = n >> 7, nn = n & 127, h = nn >> 5, f = nn & 31;
    const float* Wr = isV ? pp.Wv : pp.Wk;
    int kqvOff = isV ? 256 : 0;
    float v = 0.f;
#pragma unroll
    for (int d = 0; d < 32; d++)
        v += pp.Wkqv[(size_t)k * 384 + kqvOff + h * 32 + d] * Wr[h * 1024 + d * 32 + f];
    *(__half*)(pp.img + ((size_t)k * 256 + n) * 2) = __float2half_rn(v);
    if (k == 0) {
        float b = 0.f;
#pragma unroll
        for (int d = 0; d < 32; d++)
            b += pp.bkqv[kqvOff + h * 32 + d] * Wr[h * 1024 + d * 32 + f];
        pp.bOut[n] = b;
    }
}

// ---------------- fused, chained HMMA GEMM (128-row tiles) ----------------
// MODE 0: A = fp32 x_in; tile0 = relu(x@Win+b) -> X(fp16), chained.
// MODE 2: A = fp16 agg (normalized+gelu on load); tile0 = skip blend, chained.
struct Tile {
    const unsigned char* img;
    const float* bias;
    float* out;            // float* or (reinterpret) __half* when fp16out
    int imgNC;
    int colBase;
    int stride;            // in elements of the output type
    int fp16out;
};
struct Seg {
    const void* A;              // fp32 (MODE0) or fp16 (MODE2)
    const __half* Xold;         // fp16 skip source
    const float* denom;
    const float* skip;
    int ctaStart;
    int M;
    int nTiles;
    int pad;
    Tile t[8];
};
struct SegList { Seg s[3]; int nSeg; };

// smem: A(fp16,128 rows) 0..34815, BB0 34816, BB1 69632
#define GS 272
#define SMEM_TOT 104448

__device__ __forceinline__ void issue_tile(uint32_t smu, const Tile& tile, int buf, int tid)
{
    uint32_t bufBase = smu + 34816 + (uint32_t)buf * 34816;
#pragma unroll
    for (int j = 0; j < 8; j++) {
        int idx = j * 256 + tid;         // 0..2047
        int row = idx >> 4, q = idx & 15;
        const unsigned char* src = tile.img
            + ((size_t)row * tile.imgNC + tile.colBase) * 2 + q * 16;
        cp16(bufBase + row * GS + q * 16, src);
    }
    asm volatile("cp.async.commit_group;" ::: "memory");
}

template <int MODE>
__global__ void __launch_bounds__(256, 2) gemm_fused(SegList SL)
{
    extern __shared__ char sm[];
    const int tid = threadIdx.x, lane = tid & 31, w = tid >> 5;
    const uint32_t smu = smem_to_u32(sm);

    int si = 0;
    if (SL.nSeg > 1 && (int)blockIdx.x >= SL.s[1].ctaStart) si = 1;
    if (SL.nSeg > 2 && (int)blockIdx.x >= SL.s[2].ctaStart) si = 2;
    const Seg& sg = SL.s[si];
    const int rowBase = ((int)blockIdx.x - sg.ctaStart) * 128;
    const int M = sg.M;
    const int nT = sg.nTiles;

    // prefetch B tile 0
    issue_tile(smu, sg.t[0], 0, tid);

    // ---- A load (128 rows) + (normalize/gelu) + fp16 convert ----
#pragma unroll
    for (int j = 0; j < 16; j++) {
        int f = j * 256 + tid;               // 0..4095 quad-groups
        int row = f >> 5, col = (f & 31) * 4;
        float4 v = make_float4(0.f, 0.f, 0.f, 0.f);
        int gr = rowBase + row;
        if (gr < M) {
            if (MODE == 0) {
                v = *(const float4*)((const float*)sg.A + (size_t)gr * 128 + col);
            } else {
                uint2 u = *(const uint2*)((const __half*)sg.A + (size_t)gr * 128 + col);
                float2 f01 = __half22float2(*(__half2*)&u.x);
                float2 f23 = __half22float2(*(__half2*)&u.y);
                float inv = 1.f / fmaxf(sg.denom[(size_t)gr * 4 + (col >> 5)], 1e-16f);
                v.x = gelu_f(f01.x * inv); v.y = gelu_f(f01.y * inv);
                v.z = gelu_f(f23.x * inv); v.w = gelu_f(f23.y * inv);
            }
        }
        uint32_t p01, p23;
        asm("cvt.rn.f16x2.f32 %0, %1, %2;" : "=r"(p01) : "f"(v.y), "f"(v.x));
        asm("cvt.rn.f16x2.f32 %0, %1, %2;" : "=r"(p23) : "f"(v.w), "f"(v.z));
        *(uint2*)(sm + row * GS + col * 2) = make_uint2(p01, p23);
    }

    float sg_g = 0.f, og = 0.f;
    if (MODE == 2) { sg_g = 1.f / (1.f + expf(-*sg.skip)); og = 1.f - sg_g; }

    // warp tiling: 32 rows x 64 cols. wm in {0..3}, wn in {0,1}
    const int wm = w & 3, wn = w >> 2;
    const int lr = lane & 15, lc = lane >> 4;
    const uint32_t aB0 = smu + (wm * 32 + lr) * GS + lc * 16;
    const uint32_t aB1 = aB0 + 16 * GS;
    const uint32_t bOff = lr * GS + (wn * 64 + lc * 8) * 2;
    const int gid = lane >> 2, tc = (lane & 3) * 2;

    float acc[2][8][4];

    for (int ti = 0; ti < nT; ti++) {
        if (ti + 1 < nT) issue_tile(smu, sg.t[ti + 1], (ti + 1) & 1, tid);

        if (ti + 1 < nT) asm volatile("cp.async.wait_group 1;" ::: "memory");
        else             asm volatile("cp.async.wait_group 0;" ::: "memory");
        __syncthreads();   // also orders tile0's smem-A rewrite before chained MMAs

#pragma unroll
        for (int mi = 0; mi < 2; mi++)
#pragma unroll
            for (int nj = 0; nj < 8; nj++)
#pragma unroll
                for (int q = 0; q < 4; q++) acc[mi][nj][q] = 0.f;

        const uint32_t bB = smu + 34816 + (uint32_t)(ti & 1) * 34816 + bOff;

#pragma unroll
        for (int ks = 0; ks < 8; ks++) {
            uint32_t ah[2][4], bh[4][4];
            ldm_x4(ah[0], aB0 + ks * 32);
            ldm_x4(ah[1], aB1 + ks * 32);
#pragma unroll
            for (int nb = 0; nb < 4; nb++)
                ldm_x4_t(bh[nb], bB + ks * 16 * GS + nb * 32);
#pragma unroll
            for (int mi = 0; mi < 2; mi++)
#pragma unroll
                for (int nj = 0; nj < 8; nj++)
                    mma_f16(acc[mi][nj], ah[mi], &bh[nj >> 1][(nj & 1) * 2]);
        }
        __syncthreads();   // release this B buffer

        const Tile& tile = sg.t[ti];
        if (ti == 0) {
            // ---- activation epilogue; re-deposit into smem A (fp16) for chain ----
#pragma unroll
            for (int mi = 0; mi < 2; mi++) {
#pragma unroll
                for (int nj = 0; nj < 8; nj++) {
                    int col = wn * 64 + nj * 8 + tc;
                    float b0 = __ldg(tile.bias + col), b1 = __ldg(tile.bias + col + 1);
#pragma unroll
                    for (int half = 0; half < 2; half++) {
                        int lrow = wm * 32 + mi * 16 + gid + half * 8;
                        int row = rowBase + lrow;
                        float o0 = acc[mi][nj][half * 2 + 0] + b0;
                        float o1 = acc[mi][nj][half * 2 + 1] + b1;
                        if (MODE == 0) {
                            o0 = fmaxf(o0, 0.f); o1 = fmaxf(o1, 0.f);
                        } else {
                            float2 xo = make_float2(0.f, 0.f);
                            if (row < M)
                                xo = __half22float2(
                                    *(const __half2*)(sg.Xold + (size_t)row * 128 + col));
                            o0 = sg_g * o0 + og * xo.x;
                            o1 = sg_g * o1 + og * xo.y;
                        }
                        if (row < M) {
                            if (tile.fp16out)
                                *(__half2*)((__half*)tile.out + (size_t)row * tile.stride + col)
                                    = __floats2half2_rn(o0, o1);
                            else
                                *(float2*)(tile.out + (size_t)row * tile.stride + col)
                                    = make_float2(o0, o1);
                        }
                        if (nT > 1)
                            *(__half2*)(sm + lrow * GS + col * 2) = __floats2half2_rn(o0, o1);
                    }
                }
            }
        } else {
            // ---- plain epilogue (Q / KV, fp16 out) ----
#pragma unroll
            for (int mi = 0; mi < 2; mi++) {
#pragma unroll
                for (int nj = 0; nj < 8; nj++) {
                    int col = wn * 64 + nj * 8 + tc;
                    float b0 = __ldg(tile.bias + col), b1 = __ldg(tile.bias + col + 1);
#pragma unroll
                    for (int half = 0; half < 2; half++) {
                        int row = rowBase + wm * 32 + mi * 16 + gid + half * 8;
                        if (row >= M) continue;
                        float o0 = acc[mi][nj][half * 2 + 0] + b0;
                        float o1 = acc[mi][nj][half * 2 + 1] + b1;
                        *(__half2*)((__half*)tile.out + (size_t)row * tile.stride + col)
                            = __floats2half2_rn(o0, o1);
                    }
                }
            }
        }
    }
}

// ---------------- CSR build ----------------
__global__ void zero_counts()
{
    int i = blockIdx.x * blockDim.x + threadIdx.x;
    if (i < NN) g_counts[i] = 0;
}

__device__ __forceinline__ void edge_map(int gw,
    const int* s0, const int* d0, const int* s1, const int* d1,
    const int* s2, const int* d2, const int* s3, const int* d3,
    int& kvi, int& dg)
{
    const int* sp; const int* dp; int kvoff, doff, e = gw;
    if (gw < 150000)      { sp = s0; dp = d0; kvoff = 0;      doff = 0; }
    else if (gw < 300000) { sp = s1; dp = d1; kvoff = 100000; doff = 200000; e -= 150000; }
    else if (gw < 500000) { sp = s2; dp = d2; kvoff = 300000; doff = 0;      e -= 300000; }
    else                  { sp = s3; dp = d3; kvoff = 500000; doff = 300000; e -= 500000; }
    kvi = sp[e] + kvoff;
    dg  = dp[e] + doff;
}

__global__ void hist_edges(const int* s0, const int* d0, const int* s1, const int* d1,
                           const int* s2, const int* d2, const int* s3, const int* d3)
{
    int gw = blockIdx.x * blockDim.x + threadIdx.x;
    if (gw >= E_TOT) return;
    int kvi, dg;
    edge_map(gw, s0, d0, s1, d1, s2, d2, s3, d3, kvi, dg);
    atomicAdd(&g_counts[dg], 1);
}

__global__ void scan_blocks()
{
    __shared__ int smv[1024];
    int i = blockIdx.x * 1024 + threadIdx.x;
    int v = (i < NN) ? g_counts[i] : 0;
    smv[threadIdx.x] = v;
    __syncthreads();
#pragma unroll
    for (int off = 1; off < 1024; off <<= 1) {
        int t = (threadIdx.x >= off) ? smv[threadIdx.x - off] : 0;
        __syncthreads();
        smv[threadIdx.x] += t;
        __syncthreads();
    }
    if (i < NN) g_starts[i] = smv[threadIdx.x] - v;
    if (threadIdx.x == 1023) g_bsums[blockIdx.x] = smv[1023];
}

__global__ void scan_sums(int nb)
{
    __shared__ int smv[1024];
    int v = (threadIdx.x < nb) ? g_bsums[threadIdx.x] : 0;
    smv[threadIdx.x] = v;
    __syncthreads();
#pragma unroll
    for (int off = 1; off < 1024; off <<= 1) {
        int t = (threadIdx.x >= off) ? smv[threadIdx.x - off] : 0;
        __syncthreads();
        smv[threadIdx.x] += t;
        __syncthreads();
    }
    if (threadIdx.x < nb) g_boffs[threadIdx.x] = smv[threadIdx.x] - v;
}

__global__ void scan_finish()
{
    int i = blockIdx.x * 1024 + threadIdx.x;
    if (i < NN) {
        int s = g_starts[i] + g_boffs[blockIdx.x];
        g_starts[i] = s;
        g_cursor[i] = s;
    }
}

__global__ void scatter_edges(const int* s0, const int* d0, const int* s1, const int* d1,
                              const int* s2, const int* d2, const int* s3, const int* d3)
{
    int gw = blockIdx.x * blockDim.x + threadIdx.x;
    if (gw >= E_TOT) return;
    int kvi, dg;
    edge_map(gw, s0, d0, s1, d1, s2, d2, s3, d3, kvi, dg);
    int pos = atomicAdd(&g_cursor[dg], 1);
    g_eidx[pos] = (unsigned int)kvi;
}

// ---------------- gather: warp per dst node, pipelined edge loop ----------------
__global__ void __launch_bounds__(256) gather_nodes(
    const __half* __restrict__ KV, const __half* __restrict__ Q,
    const float* __restrict__ prel, float* __restrict__ denom, __half* __restrict__ agg)
{
    int n    = (blockIdx.x * blockDim.x + threadIdx.x) >> 5;
    int lane = threadIdx.x & 31;
    if (n >= NN) return;

    uint2 qq = *(const uint2*)(Q + (size_t)n * 128 + lane * 4);
    float2 q01 = __half22float2(*(__half2*)&qq.x);
    float2 q23 = __half22float2(*(__half2*)&qq.y);
    int start = g_starts[n];
    int cnt   = g_counts[n];
    int h = lane >> 3;

    float a0 = 0.f, a1 = 0.f, a2 = 0.f, a3 = 0.f, dsum = 0.f;

    for (int base = 0; base < cnt; base += 32) {
        int cc = min(cnt - base, 32);
        // lane-parallel prefetch of edge indices for this chunk
        unsigned kvv = 0;
        if (lane < cc) kvv = g_eidx[start + base + lane];

        // pipelined loads: issue edge j+1's K/V while reducing edge j
        int kvi = (int)__shfl_sync(0xffffffffu, kvv, 0);
        const __half* kvrow = KV + (size_t)kvi * 256;
        uint2 kk = *(const uint2*)(kvrow + lane * 4);
        uint2 vv = *(const uint2*)(kvrow + 128 + lane * 4);

        for (int j = 0; j < cc; j++) {
            uint2 kc = kk, vc = vv;
            int kvic = kvi;
            if (j + 1 < cc) {
                kvi = (int)__shfl_sync(0xffffffffu, kvv, j + 1);
                kvrow = KV + (size_t)kvi * 256;
                kk = *(const uint2*)(kvrow + lane * 4);
                vv = *(const uint2*)(kvrow + 128 + lane * 4);
            }
            int r = (kvic < 100000) ? 0 : (kvic < 300000) ? 1 : (kvic < 500000) ? 2 : 3;
            float2 k01 = __half22float2(*(__half2*)&kc.x);
            float2 k23 = __half22float2(*(__half2*)&kc.y);
            float p = k01.x * q01.x + k01.y * q01.y + k23.x * q23.x + k23.y * q23.y;
            p += __shfl_xor_sync(0xffffffffu, p, 1);
            p += __shfl_xor_sync(0xffffffffu, p, 2);
            p += __shfl_xor_sync(0xffffffffu, p, 4);
            float a  = p * __ldg(prel + r * 4 + h) * 0.17677669529663687f;
            float ea = expf(a);
            dsum += ea;
            float2 v01 = __half22float2(*(__half2*)&vc.x);
            float2 v23 = __half22float2(*(__half2*)&vc.y);
            a0 += ea * v01.x; a1 += ea * v01.y; a2 += ea * v23.x; a3 += ea * v23.y;
        }
    }

    __half2 h01 = __floats2half2_rn(a0, a1);
    __half2 h23 = __floats2half2_rn(a2, a3);
    uint2 st;
    st.x = *(uint32_t*)&h01;
    st.y = *(uint32_t*)&h23;
    *(uint2*)(agg + (size_t)n * 128 + lane * 4) = st;
    if ((lane & 7) == 0) denom[(size_t)n * 4 + h] = dsum;
}

// ---------------- host launch ----------------
extern "C" void kernel_launch(void* const* d_in, const int* in_sizes, int n_in,
                              void* d_out, int out_size)
{
    (void)in_sizes; (void)n_in; (void)out_size;

    const float* x_in[3] = {(const float*)d_in[0], (const float*)d_in[1], (const float*)d_in[2]};
    const int* esrc[4]; const int* edst[4];
    for (int r = 0; r < 4; r++) { esrc[r] = (const int*)d_in[3 + 2*r]; edst[r] = (const int*)d_in[4 + 2*r]; }
    const float* W_in   = (const float*)d_in[11];
    const float* b_in   = (const float*)d_in[12];
    const float* Wkqv   = (const float*)d_in[13];
    const float* bkqv   = (const float*)d_in[14];
    const float* Wk_rel = (const float*)d_in[15];
    const float* Wv_rel = (const float*)d_in[16];
    const float* p_rel  = (const float*)d_in[17];
    const float* Wout   = (const float*)d_in[18];
    const float* bout   = (const float*)d_in[19];
    const float* skip   = (const float*)d_in[20];
    float* out = (float*)d_out;

    float *denom, *bias;
    __half *X, *Q, *KV, *agg;
    unsigned char* wimg;
    cudaGetSymbolAddress((void**)&X,     g_X);
    cudaGetSymbolAddress((void**)&Q,     g_Q);
    cudaGetSymbolAddress((void**)&KV,    g_KV);
    cudaGetSymbolAddress((void**)&denom, g_denom);
    cudaGetSymbolAddress((void**)&agg,   g_agg);
    cudaGetSymbolAddress((void**)&wimg,  g_wimg);
    cudaGetSymbolAddress((void**)&bias,  g_bias);

    cudaFuncSetAttribute(gemm_fused<0>, cudaFuncAttributeMaxDynamicSharedMemorySize, SMEM_TOT);
    cudaFuncSetAttribute(gemm_fused<2>, cudaFuncAttributeMaxDynamicSharedMemorySize, SMEM_TOT);

    const int NB = (NN + 1023) / 1024;
    const int CTA_P = (NP + 127) / 128, CTA_A = (NA + 127) / 128, CTA_K = (NKW + 127) / 128;
    const int CTA_ALL = CTA_P + CTA_A + CTA_K;
    const int starts[3] = {0, CTA_P, CTA_P + CTA_A};

    // ---- weight preps ----
    {
        PPlainList L;
        for (int t = 0; t < 3; t++)
            L.p[t] = { W_in + (size_t)t*C*C, 128, b_in + t*128, wimg + IMG_IN(t), bias + B_IN(t) };
        for (int l = 0; l < LAYERS; l++)
            for (int t = 0; t < 3; t++) {
                L.p[3 + l*3 + t] = { Wkqv + (size_t)(l*3 + t)*C*384 + 128, 384,
                                     bkqv + (size_t)(l*3 + t)*384 + 128,
                                     wimg + IMG_Q(l,t), bias + B_Q(l,t) };
                L.p[9 + l*3 + t] = { Wout + (size_t)(l*3 + t)*C*C, 128,
                                     bout + (size_t)(l*3 + t)*128,
                                     wimg + IMG_OUT(l,t), bias + B_OUT(l,t) };
            }
        dim3 grid(64, 15);
        prep_plain_all<<<grid, 256>>>(L);
    }
    {
        static const int REL_ST_L[4] = {1, 0, 0, 0};
        PKVList L;
        for (int l = 0; l < LAYERS; l++)
            for (int r = 0; r < NR; r++) {
                int st = REL_ST_L[r];
                L.p[l*4 + r] = { Wkqv + (size_t)(l*3 + st)*C*384, bkqv + (size_t)(l*3 + st)*384,
                                 Wk_rel + (size_t)(l*NR + r)*4096, Wv_rel + (size_t)(l*NR + r)*4096,
                                 wimg + IMG_KV(l,r), bias + B_KV(l,r) };
            }
        dim3 grid(128, 8);
        prep_kv_all<<<grid, 256>>>(L);
    }

    // ---- CSR histogram ----
    zero_counts<<<(NN + 255)/256, 256>>>();
    hist_edges<<<(E_TOT + 255)/256, 256>>>(esrc[0], edst[0], esrc[1], edst[1],
                                           esrc[2], edst[2], esrc[3], edst[3]);

    // helper to fill chain tiles (Q + KV of layer l) for node type t, starting at index base
    auto fill_chain = [&](Seg& sgm, int l, int t, int base) {
        sgm.t[base] = { wimg + IMG_Q(l,t), bias + B_Q(l,t),
                        (float*)(Q + (size_t)OFFS_H[t]*C), 128, 0, 128, 1 };
        int k = base + 1;
        if (t == 0) {
            for (int r = 1; r <= 3; r++)
                for (int c = 0; c < 2; c++)
                    sgm.t[k++] = { wimg + IMG_KV(l,r), bias + B_KV(l,r) + c*128,
                                   (float*)(KV + (size_t)KRELOFF_H[r]*256 + c*128), 256, c*128, 256, 1 };
        } else if (t == 1) {
            for (int c = 0; c < 2; c++)
                sgm.t[k++] = { wimg + IMG_KV(l,0), bias + B_KV(l,0) + c*128,
                               (float*)(KV + (size_t)KRELOFF_H[0]*256 + c*128), 256, c*128, 256, 1 };
        }
        sgm.nTiles = k;
    };

    // ---- fused input linear+relu -> X(fp16), chained into layer-0 Q/KV ----
    {
        SegList SL; SL.nSeg = 3;
        for (int t = 0; t < 3; t++) {
            Seg& sgm = SL.s[t];
            sgm.A = x_in[t]; sgm.Xold = nullptr; sgm.denom = nullptr; sgm.skip = nullptr;
            sgm.ctaStart = starts[t]; sgm.M = NT_H[t];
            sgm.t[0] = { wimg + IMG_IN(t), bias + B_IN(t),
                         (float*)(X + (size_t)OFFS_H[t]*C), 128, 0, 128, 1 };
            fill_chain(sgm, 0, t, 1);
        }
        gemm_fused<0><<<CTA_ALL, 256, SMEM_TOT>>>(SL);
    }

    // ---- finish CSR build ----
    scan_blocks<<<NB, 1024>>>();
    scan_sums<<<1, 1024>>>(NB);
    scan_finish<<<NB, 1024>>>();
    scatter_edges<<<(E_TOT + 255)/256, 256>>>(esrc[0], edst[0], esrc[1], edst[1],
                                              esrc[2], edst[2], esrc[3], edst[3]);

    // ---- layer 0: gather, then outproj0 chained into layer-1 Q/KV ----
    gather_nodes<<<(NN * 32 + 255)/256, 256>>>(KV, Q, p_rel + 0, denom, agg);
    {
        SegList SL; SL.nSeg = 3;
        for (int t = 0; t < 3; t++) {
            Seg& sgm = SL.s[t];
            sgm.A = agg + (size_t)OFFS_H[t]*C;
            sgm.Xold = X + (size_t)OFFS_H[t]*C;
            sgm.denom = denom + (size_t)OFFS_H[t]*H;
            sgm.skip = skip + (size_t)(0*3 + t);
            sgm.ctaStart = starts[t]; sgm.M = NT_H[t];
            sgm.t[0] = { wimg + IMG_OUT(0,t), bias + B_OUT(0,t),
                         (float*)(X + (size_t)OFFS_H[t]*C), 128, 0, 128, 1 };
            fill_chain(sgm, 1, t, 1);
        }
        gemm_fused<2><<<CTA_ALL, 256, SMEM_TOT>>>(SL);
    }

    // ---- layer 1: gather, then final outproj -> out (fp32) ----
    gather_nodes<<<(NN * 32 + 255)/256, 256>>>(KV, Q, p_rel + (size_t)NR*H, denom, agg);
    {
        SegList SL; SL.nSeg = 3;
        for (int t = 0; t < 3; t++) {
            Seg& sgm = SL.s[t];
            sgm.A = agg + (size_t)OFFS_H[t]*C;
            sgm.Xold = X + (size_t)OFFS_H[t]*C;
            sgm.denom = denom + (size_t)OFFS_H[t]*H;
            sgm.skip = skip + (size_t)(1*3 + t);
            sgm.ctaStart = starts[t]; sgm.M = NT_H[t];
            sgm.nTiles = 1;
            sgm.t[0] = { wimg + IMG_OUT(1,t), bias + B_OUT(1,t),
                         out + (size_t)OFFS_H[t]*C, 128, 0, 128, 0 };
        }
        gemm_fused<2><<<CTA_ALL, 256, SMEM_TOT>>>(SL);
    }
}

// round 16
// speedup vs baseline: 1.0640x; 1.0640x over previous
#include <cuda_runtime.h>
#include <cuda_fp16.h>
#include <math.h>
#include <stdint.h>

// ---------------- problem constants ----------------
#define NP 200000
#define NA 100000
#define NKW 50000
#define NN 350000
#define C 128
#define H 4
#define D 32
#define LAYERS 2
#define NR 4
#define E_TOT 600000
#define SRC_TOT 700000   // rel0: A(100k) srcs, rel1-3: P(200k) each

static const int OFFS_H[3]     = {0, NP, NP + NA};
static const int KRELOFF_H[4]  = {0, NA, NA + NP, NA + 2*NP};
static const int NT_H[3]       = {NP, NA, NKW};

// ---------------- scratch ----------------
__device__ __half g_X    [(size_t)NN * C];           // fp16 X (skip source)
__device__ __half g_Q    [(size_t)NN * C];           // fp16 Q
__device__ __half g_KV   [(size_t)SRC_TOT * 256];    // fp16 [Krel(128) | Vrel(128)]
__device__ float  g_denom[(size_t)NN * H];
__device__ __half g_agg  [(size_t)NN * C];           // fp16 unnormalized agg
__device__ unsigned char g_wimg[2031616];
__device__ float  g_bias[3968];
// CSR (built once)
__device__ int g_counts[NN];
__device__ int g_starts[NN];
__device__ int g_cursor[NN];
__device__ int g_bsums[512];
__device__ int g_boffs[512];
__device__ unsigned int g_eidx[E_TOT];

#define IMG_IN(t)     ((size_t)(t) * 65536)
#define IMG_Q(l,t)    ((size_t)(3 + (l)*3 + (t)) * 65536)
#define IMG_OUT(l,t)  ((size_t)(9 + (l)*3 + (t)) * 65536)
#define IMG_KV(l,r)   ((size_t)15 * 65536 + (size_t)((l)*4 + (r)) * 131072)
#define B_IN(t)     ((t) * 128)
#define B_Q(l,t)    (384 + ((l)*3 + (t)) * 128)
#define B_OUT(l,t)  (1152 + ((l)*3 + (t)) * 128)
#define B_KV(l,r)   (1920 + ((l)*4 + (r)) * 256)

// ---------------- helpers ----------------
__device__ __forceinline__ uint32_t smem_to_u32(const void* p) {
    uint32_t a;
    asm("{ .reg .u64 t; cvta.to.shared.u64 t, %1; cvt.u32.u64 %0, t; }" : "=r"(a) : "l"(p));
    return a;
}
__device__ __forceinline__ float gelu_f(float x) {
    return 0.5f * x * (1.0f + erff(x * 0.70710678118654752440f));
}
__device__ __forceinline__ void ldm_x4(uint32_t* r, uint32_t a) {
    asm volatile("ldmatrix.sync.aligned.m8n8.x4.shared.b16 {%0,%1,%2,%3}, [%4];"
                 : "=r"(r[0]), "=r"(r[1]), "=r"(r[2]), "=r"(r[3]) : "r"(a));
}
__device__ __forceinline__ void ldm_x4_t(uint32_t* r, uint32_t a) {
    asm volatile("ldmatrix.sync.aligned.m8n8.x4.trans.shared.b16 {%0,%1,%2,%3}, [%4];"
                 : "=r"(r[0]), "=r"(r[1]), "=r"(r[2]), "=r"(r[3]) : "r"(a));
}
__device__ __forceinline__ void mma_f16(float* d, const uint32_t* a, const uint32_t* b) {
    asm volatile(
        "mma.sync.aligned.m16n8k16.row.col.f32.f16.f16.f32 "
        "{%0,%1,%2,%3}, {%4,%5,%6,%7}, {%8,%9}, {%0,%1,%2,%3};"
        : "+f"(d[0]), "+f"(d[1]), "+f"(d[2]), "+f"(d[3])
        : "r"(a[0]), "r"(a[1]), "r"(a[2]), "r"(a[3]), "r"(b[0]), "r"(b[1]));
}
__device__ __forceinline__ void cp16(uint32_t dst, const void* src) {
    asm volatile("cp.async.cg.shared.global [%0], [%1], 16;" :: "r"(dst), "l"(src));
}

// ---------------- batched weight prep: fp32 -> fp16 image ----------------
struct PPlain { const float* W; long ldW; const float* bias; unsigned char* img; float* bOut; };
struct PPlainList { PPlain p[15]; };

__global__ void prep_plain_all(PPlainList L)
{
    const PPlain pp = L.p[blockIdx.y];
    int idx = blockIdx.x * blockDim.x + threadIdx.x;
    int n = idx & 127, k = idx >> 7;
    float v = pp.W[(size_t)k * pp.ldW + n];
    *(__half*)(pp.img + ((size_t)k * 128 + n) * 2) = __float2half_rn(v);
    if (k == 0) pp.bOut[n] = pp.bias[n];
}

struct PKV { const float* Wkqv; const float* bkqv; const float* Wk; const float* Wv;
             unsigned char* img; float* bOut; };
struct PKVList { PKV p[8]; };

__global__ void prep_kv_all(PKVList L)
{
    const PKV pp = L.p[blockIdx.y];
    int idx = blockIdx.x * blockDim.x + threadIdx.x;
    int n = idx & 255, k = idx >> 8;
    int isV = n >> 7, nn = n & 127, h = nn >> 5, f = nn & 31;
    const float* Wr = isV ? pp.Wv : pp.Wk;
    int kqvOff = isV ? 256 : 0;
    float v = 0.f;
#pragma unroll
    for (int d = 0; d < 32; d++)
        v += pp.Wkqv[(size_t)k * 384 + kqvOff + h * 32 + d] * Wr[h * 1024 + d * 32 + f];
    *(__half*)(pp.img + ((size_t)k * 256 + n) * 2) = __float2half_rn(v);
    if (k == 0) {
        float b = 0.f;
#pragma unroll
        for (int d = 0; d < 32; d++)
            b += pp.bkqv[kqvOff + h * 32 + d] * Wr[h * 1024 + d * 32 + f];
        pp.bOut[n] = b;
    }
}

// ---------------- fused, chained HMMA GEMM (64-row tiles, half-tile pipeline, 3 CTA/SM) ----
struct Tile {
    const unsigned char* img;
    const float* bias;
    float* out;            // float* or (reinterpret) __half* when fp16out
    int imgNC;
    int colBase;
    int stride;            // in elements of the output type
    int fp16out;
};
struct Seg {
    const void* A;              // fp32 (MODE0) or fp16 (MODE2)
    const __half* Xold;         // fp16 skip source
    const float* denom;
    const float* skip;
    int ctaStart;
    int M;
    int nTiles;
    int pad;
    Tile t[8];
};
struct SegList { Seg s[3]; int nSeg; };

// smem: A(fp16, 64 rows) 0..17407, BB0 17408 (17408 B), BB1 34816 (17408 B)
#define GS 272
#define SMEM_TOT 52224

// half s of the tile sequence: tile = s>>1, k-half = s&1, buffer = s&1
__device__ __forceinline__ void issue_half(uint32_t smu, const Tile& tile, int s, int tid)
{
    int h = s & 1;
    uint32_t bufBase = smu + 17408 + (uint32_t)(s & 1) * 17408;
#pragma unroll
    for (int j = 0; j < 4; j++) {
        int idx = j * 256 + tid;         // 0..1023 uint4 (64 rows x 256B)
        int row = idx >> 4, q = idx & 15;
        const unsigned char* src = tile.img
            + ((size_t)(h * 64 + row) * tile.imgNC + tile.colBase) * 2 + q * 16;
        cp16(bufBase + row * GS + q * 16, src);
    }
    asm volatile("cp.async.commit_group;" ::: "memory");
}

template <int MODE>
__global__ void __launch_bounds__(256, 3) gemm_fused(SegList SL)
{
    extern __shared__ char sm[];
    const int tid = threadIdx.x, lane = tid & 31, w = tid >> 5;
    const uint32_t smu = smem_to_u32(sm);

    int si = 0;
    if (SL.nSeg > 1 && (int)blockIdx.x >= SL.s[1].ctaStart) si = 1;
    if (SL.nSeg > 2 && (int)blockIdx.x >= SL.s[2].ctaStart) si = 2;
    const Seg& sg = SL.s[si];
    const int rowBase = ((int)blockIdx.x - sg.ctaStart) * 64;
    const int M = sg.M;
    const int nHalf = sg.nTiles * 2;

    // prefetch first two B halves
    issue_half(smu, sg.t[0], 0, tid);
    issue_half(smu, sg.t[0], 1, tid);

    // ---- A load (64 rows) + (normalize/gelu) + fp16 convert ----
#pragma unroll
    for (int j = 0; j < 8; j++) {
        int f = j * 256 + tid;
        int row = f >> 5, col = (f & 31) * 4;
        float4 v = make_float4(0.f, 0.f, 0.f, 0.f);
        int gr = rowBase + row;
        if (gr < M) {
            if (MODE == 0) {
                v = *(const float4*)((const float*)sg.A + (size_t)gr * 128 + col);
            } else {
                uint2 u = *(const uint2*)((const __half*)sg.A + (size_t)gr * 128 + col);
                float2 f01 = __half22float2(*(__half2*)&u.x);
                float2 f23 = __half22float2(*(__half2*)&u.y);
                float inv = 1.f / fmaxf(sg.denom[(size_t)gr * 4 + (col >> 5)], 1e-16f);
                v.x = gelu_f(f01.x * inv); v.y = gelu_f(f01.y * inv);
                v.z = gelu_f(f23.x * inv); v.w = gelu_f(f23.y * inv);
            }
        }
        uint32_t p01, p23;
        asm("cvt.rn.f16x2.f32 %0, %1, %2;" : "=r"(p01) : "f"(v.y), "f"(v.x));
        asm("cvt.rn.f16x2.f32 %0, %1, %2;" : "=r"(p23) : "f"(v.w), "f"(v.z));
        *(uint2*)(sm + row * GS + col * 2) = make_uint2(p01, p23);
    }

    float sg_g = 0.f, og = 0.f;
    if (MODE == 2) { sg_g = 1.f / (1.f + expf(-*sg.skip)); og = 1.f - sg_g; }

    // warp tiling: 32 rows x 32 cols. wm in {0,1}, wn in {0..3}
    const int wm = w & 1, wn = w >> 1;
    const int lr = lane & 15, lc = lane >> 4;
    const uint32_t aB0 = smu + (wm * 32 + lr) * GS + lc * 16;
    const uint32_t aB1 = aB0 + 16 * GS;
    const uint32_t bOff = lr * GS + (wn * 32 + lc * 8) * 2;
    const int gid = lane >> 2, tc = (lane & 3) * 2;

    float acc[2][4][4];

    for (int s = 0; s < nHalf; s++) {
        if (!(s & 1)) {
#pragma unroll
            for (int mi = 0; mi < 2; mi++)
#pragma unroll
                for (int nj = 0; nj < 4; nj++)
#pragma unroll
                    for (int q = 0; q < 4; q++) acc[mi][nj][q] = 0.f;
        }

        if (s == nHalf - 1) asm volatile("cp.async.wait_group 0;" ::: "memory");
        else                asm volatile("cp.async.wait_group 1;" ::: "memory");
        __syncthreads();   // B buffer ready; also orders tile0's smem-A rewrite

        const uint32_t bB = smu + 17408 + (uint32_t)(s & 1) * 17408 + bOff;
        const int hbase = (s & 1) * 4;

#pragma unroll
        for (int ks = 0; ks < 4; ks++) {
            uint32_t ah[2][4], bh[2][4];
            ldm_x4(ah[0], aB0 + (hbase + ks) * 32);
            ldm_x4(ah[1], aB1 + (hbase + ks) * 32);
            ldm_x4_t(bh[0], bB + ks * 16 * GS);
            ldm_x4_t(bh[1], bB + ks * 16 * GS + 32);
#pragma unroll
            for (int mi = 0; mi < 2; mi++)
#pragma unroll
                for (int nj = 0; nj < 4; nj++)
                    mma_f16(acc[mi][nj], ah[mi], &bh[nj >> 1][(nj & 1) * 2]);
        }
        __syncthreads();   // release this B buffer

        if (s + 2 < nHalf) issue_half(smu, sg.t[(s + 2) >> 1], s + 2, tid);

        if (s & 1) {
            const Tile& tile = sg.t[s >> 1];
            if ((s >> 1) == 0) {
                // ---- activation epilogue; re-deposit into smem A (fp16) for chain ----
#pragma unroll
                for (int mi = 0; mi < 2; mi++) {
#pragma unroll
                    for (int nj = 0; nj < 4; nj++) {
                        int col = wn * 32 + nj * 8 + tc;
                        float b0 = __ldg(tile.bias + col), b1 = __ldg(tile.bias + col + 1);
#pragma unroll
                        for (int half = 0; half < 2; half++) {
                            int lrow = wm * 32 + mi * 16 + gid + half * 8;
                            int row = rowBase + lrow;
                            float o0 = acc[mi][nj][half * 2 + 0] + b0;
                            float o1 = acc[mi][nj][half * 2 + 1] + b1;
                            if (MODE == 0) {
                                o0 = fmaxf(o0, 0.f); o1 = fmaxf(o1, 0.f);
                            } else {
                                float2 xo = make_float2(0.f, 0.f);
                                if (row < M)
                                    xo = __half22float2(
                                        *(const __half2*)(sg.Xold + (size_t)row * 128 + col));
                                o0 = sg_g * o0 + og * xo.x;
                                o1 = sg_g * o1 + og * xo.y;
                            }
                            if (row < M) {
                                if (tile.fp16out)
                                    *(__half2*)((__half*)tile.out + (size_t)row * tile.stride + col)
                                        = __floats2half2_rn(o0, o1);
                                else
                                    *(float2*)(tile.out + (size_t)row * tile.stride + col)
                                        = make_float2(o0, o1);
                            }
                            if (nHalf > 2)
                                *(__half2*)(sm + lrow * GS + col * 2) = __floats2half2_rn(o0, o1);
                        }
                    }
                }
            } else {
                // ---- plain epilogue (Q / KV, fp16 out) ----
#pragma unroll
                for (int mi = 0; mi < 2; mi++) {
#pragma unroll
                    for (int nj = 0; nj < 4; nj++) {
                        int col = wn * 32 + nj * 8 + tc;
                        float b0 = __ldg(tile.bias + col), b1 = __ldg(tile.bias + col + 1);
#pragma unroll
                        for (int half = 0; half < 2; half++) {
                            int row = rowBase + wm * 32 + mi * 16 + gid + half * 8;
                            if (row >= M) continue;
                            float o0 = acc[mi][nj][half * 2 + 0] + b0;
                            float o1 = acc[mi][nj][half * 2 + 1] + b1;
                            *(__half2*)((__half*)tile.out + (size_t)row * tile.stride + col)
                                = __floats2half2_rn(o0, o1);
                        }
                    }
                }
            }
        }
    }
}

// ---------------- CSR build ----------------
__global__ void zero_counts()
{
    int i = blockIdx.x * blockDim.x + threadIdx.x;
    if (i < NN) g_counts[i] = 0;
}

__device__ __forceinline__ void edge_map(int gw,
    const int* s0, const int* d0, const int* s1, const int* d1,
    const int* s2, const int* d2, const int* s3, const int* d3,
    int& kvi, int& dg)
{
    const int* sp; const int* dp; int kvoff, doff, e = gw;
    if (gw < 150000)      { sp = s0; dp = d0; kvoff = 0;      doff = 0; }
    else if (gw < 300000) { sp = s1; dp = d1; kvoff = 100000; doff = 200000; e -= 150000; }
    else if (gw < 500000) { sp = s2; dp = d2; kvoff = 300000; doff = 0;      e -= 300000; }
    else                  { sp = s3; dp = d3; kvoff = 500000; doff = 300000; e -= 500000; }
    kvi = sp[e] + kvoff;
    dg  = dp[e] + doff;
}

__global__ void hist_edges(const int* s0, const int* d0, const int* s1, const int* d1,
                           const int* s2, const int* d2, const int* s3, const int* d3)
{
    int gw = blockIdx.x * blockDim.x + threadIdx.x;
    if (gw >= E_TOT) return;
    int kvi, dg;
    edge_map(gw, s0, d0, s1, d1, s2, d2, s3, d3, kvi, dg);
    atomicAdd(&g_counts[dg], 1);
}

__global__ void scan_blocks()
{
    __shared__ int smv[1024];
    int i = blockIdx.x * 1024 + threadIdx.x;
    int v = (i < NN) ? g_counts[i] : 0;
    smv[threadIdx.x] = v;
    __syncthreads();
#pragma unroll
    for (int off = 1; off < 1024; off <<= 1) {
        int t = (threadIdx.x >= off) ? smv[threadIdx.x - off] : 0;
        __syncthreads();
        smv[threadIdx.x] += t;
        __syncthreads();
    }
    if (i < NN) g_starts[i] = smv[threadIdx.x] - v;
    if (threadIdx.x == 1023) g_bsums[blockIdx.x] = smv[1023];
}

__global__ void scan_sums(int nb)
{
    __shared__ int smv[1024];
    int v = (threadIdx.x < nb) ? g_bsums[threadIdx.x] : 0;
    smv[threadIdx.x] = v;
    __syncthreads();
#pragma unroll
    for (int off = 1; off < 1024; off <<= 1) {
        int t = (threadIdx.x >= off) ? smv[threadIdx.x - off] : 0;
        __syncthreads();
        smv[threadIdx.x] += t;
        __syncthreads();
    }
    if (threadIdx.x < nb) g_boffs[threadIdx.x] = smv[threadIdx.x] - v;
}

__global__ void scan_finish()
{
    int i = blockIdx.x * 1024 + threadIdx.x;
    if (i < NN) {
        int s = g_starts[i] + g_boffs[blockIdx.x];
        g_starts[i] = s;
        g_cursor[i] = s;
    }
}

__global__ void scatter_edges(const int* s0, const int* d0, const int* s1, const int* d1,
                              const int* s2, const int* d2, const int* s3, const int* d3)
{
    int gw = blockIdx.x * blockDim.x + threadIdx.x;
    if (gw >= E_TOT) return;
    int kvi, dg;
    edge_map(gw, s0, d0, s1, d1, s2, d2, s3, d3, kvi, dg);
    int pos = atomicAdd(&g_cursor[dg], 1);
    g_eidx[pos] = (unsigned int)kvi;
}

// ---------------- gather: warp per dst node, pipelined edge loop ----------------
__global__ void __launch_bounds__(256) gather_nodes(
    const __half* __restrict__ KV, const __half* __restrict__ Q,
    const float* __restrict__ prel, float* __restrict__ denom, __half* __restrict__ agg)
{
    int n    = (blockIdx.x * blockDim.x + threadIdx.x) >> 5;
    int lane = threadIdx.x & 31;
    if (n >= NN) return;

    uint2 qq = *(const uint2*)(Q + (size_t)n * 128 + lane * 4);
    float2 q01 = __half22float2(*(__half2*)&qq.x);
    float2 q23 = __half22float2(*(__half2*)&qq.y);
    int start = g_starts[n];
    int cnt   = g_counts[n];
    int h = lane >> 3;

    float a0 = 0.f, a1 = 0.f, a2 = 0.f, a3 = 0.f, dsum = 0.f;

    for (int base = 0; base < cnt; base += 32) {
        int cc = min(cnt - base, 32);
        unsigned kvv = 0;
        if (lane < cc) kvv = g_eidx[start + base + lane];

        int kvi = (int)__shfl_sync(0xffffffffu, kvv, 0);
        const __half* kvrow = KV + (size_t)kvi * 256;
        uint2 kk = *(const uint2*)(kvrow + lane * 4);
        uint2 vv = *(const uint2*)(kvrow + 128 + lane * 4);

        for (int j = 0; j < cc; j++) {
            uint2 kc = kk, vc = vv;
            int kvic = kvi;
            if (j + 1 < cc) {
                kvi = (int)__shfl_sync(0xffffffffu, kvv, j + 1);
                kvrow = KV + (size_t)kvi * 256;
                kk = *(const uint2*)(kvrow + lane * 4);
                vv = *(const uint2*)(kvrow + 128 + lane * 4);
            }
            int r = (kvic < 100000) ? 0 : (kvic < 300000) ? 1 : (kvic < 500000) ? 2 : 3;
            float2 k01 = __half22float2(*(__half2*)&kc.x);
            float2 k23 = __half22float2(*(__half2*)&kc.y);
            float p = k01.x * q01.x + k01.y * q01.y + k23.x * q23.x + k23.y * q23.y;
            p += __shfl_xor_sync(0xffffffffu, p, 1);
            p += __shfl_xor_sync(0xffffffffu, p, 2);
            p += __shfl_xor_sync(0xffffffffu, p, 4);
            float a  = p * __ldg(prel + r * 4 + h) * 0.17677669529663687f;
            float ea = expf(a);
            dsum += ea;
            float2 v01 = __half22float2(*(__half2*)&vc.x);
            float2 v23 = __half22float2(*(__half2*)&vc.y);
            a0 += ea * v01.x; a1 += ea * v01.y; a2 += ea * v23.x; a3 += ea * v23.y;
        }
    }

    __half2 h01 = __floats2half2_rn(a0, a1);
    __half2 h23 = __floats2half2_rn(a2, a3);
    uint2 st;
    st.x = *(uint32_t*)&h01;
    st.y = *(uint32_t*)&h23;
    *(uint2*)(agg + (size_t)n * 128 + lane * 4) = st;
    if ((lane & 7) == 0) denom[(size_t)n * 4 + h] = dsum;
}

// ---------------- host launch ----------------
extern "C" void kernel_launch(void* const* d_in, const int* in_sizes, int n_in,
                              void* d_out, int out_size)
{
    (void)in_sizes; (void)n_in; (void)out_size;

    const float* x_in[3] = {(const float*)d_in[0], (const float*)d_in[1], (const float*)d_in[2]};
    const int* esrc[4]; const int* edst[4];
    for (int r = 0; r < 4; r++) { esrc[r] = (const int*)d_in[3 + 2*r]; edst[r] = (const int*)d_in[4 + 2*r]; }
    const float* W_in   = (const float*)d_in[11];
    const float* b_in   = (const float*)d_in[12];
    const float* Wkqv   = (const float*)d_in[13];
    const float* bkqv   = (const float*)d_in[14];
    const float* Wk_rel = (const float*)d_in[15];
    const float* Wv_rel = (const float*)d_in[16];
    const float* p_rel  = (const float*)d_in[17];
    const float* Wout   = (const float*)d_in[18];
    const float* bout   = (const float*)d_in[19];
    const float* skip   = (const float*)d_in[20];
    float* out = (float*)d_out;

    float *denom, *bias;
    __half *X, *Q, *KV, *agg;
    unsigned char* wimg;
    cudaGetSymbolAddress((void**)&X,     g_X);
    cudaGetSymbolAddress((void**)&Q,     g_Q);
    cudaGetSymbolAddress((void**)&KV,    g_KV);
    cudaGetSymbolAddress((void**)&denom, g_denom);
    cudaGetSymbolAddress((void**)&agg,   g_agg);
    cudaGetSymbolAddress((void**)&wimg,  g_wimg);
    cudaGetSymbolAddress((void**)&bias,  g_bias);

    cudaFuncSetAttribute(gemm_fused<0>, cudaFuncAttributeMaxDynamicSharedMemorySize, SMEM_TOT);
    cudaFuncSetAttribute(gemm_fused<2>, cudaFuncAttributeMaxDynamicSharedMemorySize, SMEM_TOT);

    const int NB = (NN + 1023) / 1024;
    const int CTA_P = (NP + 63) / 64, CTA_A = (NA + 63) / 64, CTA_K = (NKW + 63) / 64;
    const int CTA_ALL = CTA_P + CTA_A + CTA_K;
    const int starts[3] = {0, CTA_P, CTA_P + CTA_A};

    // ---- weight preps ----
    {
        PPlainList L;
        for (int t = 0; t < 3; t++)
            L.p[t] = { W_in + (size_t)t*C*C, 128, b_in + t*128, wimg + IMG_IN(t), bias + B_IN(t) };
        for (int l = 0; l < LAYERS; l++)
            for (int t = 0; t < 3; t++) {
                L.p[3 + l*3 + t] = { Wkqv + (size_t)(l*3 + t)*C*384 + 128, 384,
                                     bkqv + (size_t)(l*3 + t)*384 + 128,
                                     wimg + IMG_Q(l,t), bias + B_Q(l,t) };
                L.p[9 + l*3 + t] = { Wout + (size_t)(l*3 + t)*C*C, 128,
                                     bout + (size_t)(l*3 + t)*128,
                                     wimg + IMG_OUT(l,t), bias + B_OUT(l,t) };
            }
        dim3 grid(64, 15);
        prep_plain_all<<<grid, 256>>>(L);
    }
    {
        static const int REL_ST_L[4] = {1, 0, 0, 0};
        PKVList L;
        for (int l = 0; l < LAYERS; l++)
            for (int r = 0; r < NR; r++) {
                int st = REL_ST_L[r];
                L.p[l*4 + r] = { Wkqv + (size_t)(l*3 + st)*C*384, bkqv + (size_t)(l*3 + st)*384,
                                 Wk_rel + (size_t)(l*NR + r)*4096, Wv_rel + (size_t)(l*NR + r)*4096,
                                 wimg + IMG_KV(l,r), bias + B_KV(l,r) };
            }
        dim3 grid(128, 8);
        prep_kv_all<<<grid, 256>>>(L);
    }

    // ---- CSR histogram ----
    zero_counts<<<(NN + 255)/256, 256>>>();
    hist_edges<<<(E_TOT + 255)/256, 256>>>(esrc[0], edst[0], esrc[1], edst[1],
                                           esrc[2], edst[2], esrc[3], edst[3]);

    auto fill_chain = [&](Seg& sgm, int l, int t, int base) {
        sgm.t[base] = { wimg + IMG_Q(l,t), bias + B_Q(l,t),
                        (float*)(Q + (size_t)OFFS_H[t]*C), 128, 0, 128, 1 };
        int k = base + 1;
        if (t == 0) {
            for (int r = 1; r <= 3; r++)
                for (int c = 0; c < 2; c++)
                    sgm.t[k++] = { wimg + IMG_KV(l,r), bias + B_KV(l,r) + c*128,
                                   (float*)(KV + (size_t)KRELOFF_H[r]*256 + c*128), 256, c*128, 256, 1 };
        } else if (t == 1) {
            for (int c = 0; c < 2; c++)
                sgm.t[k++] = { wimg + IMG_KV(l,0), bias + B_KV(l,0) + c*128,
                               (float*)(KV + (size_t)KRELOFF_H[0]*256 + c*128), 256, c*128, 256, 1 };
        }
        sgm.nTiles = k;
    };

    // ---- fused input linear+relu -> X(fp16), chained into layer-0 Q/KV ----
    {
        SegList SL; SL.nSeg = 3;
        for (int t = 0; t < 3; t++) {
            Seg& sgm = SL.s[t];
            sgm.A = x_in[t]; sgm.Xold = nullptr; sgm.denom = nullptr; sgm.skip = nullptr;
            sgm.ctaStart = starts[t]; sgm.M = NT_H[t];
            sgm.t[0] = { wimg + IMG_IN(t), bias + B_IN(t),
                         (float*)(X + (size_t)OFFS_H[t]*C), 128, 0, 128, 1 };
            fill_chain(sgm, 0, t, 1);
        }
        gemm_fused<0><<<CTA_ALL, 256, SMEM_TOT>>>(SL);
    }

    // ---- finish CSR build ----
    scan_blocks<<<NB, 1024>>>();
    scan_sums<<<1, 1024>>>(NB);
    scan_finish<<<NB, 1024>>>();
    scatter_edges<<<(E_TOT + 255)/256, 256>>>(esrc[0], edst[0], esrc[1], edst[1],
                                              esrc[2], edst[2], esrc[3], edst[3]);

    // ---- layer 0: gather, then outproj0 chained into layer-1 Q/KV ----
    gather_nodes<<<(NN * 32 + 255)/256, 256>>>(KV, Q, p_rel + 0, denom, agg);
    {
        SegList SL; SL.nSeg = 3;
        for (int t = 0; t < 3; t++) {
            Seg& sgm = SL.s[t];
            sgm.A = agg + (size_t)OFFS_H[t]*C;
            sgm.Xold = X + (size_t)OFFS_H[t]*C;
            sgm.denom = denom + (size_t)OFFS_H[t]*H;
            sgm.skip = skip + (size_t)(0*3 + t);
            sgm.ctaStart = starts[t]; sgm.M = NT_H[t];
            sgm.t[0] = { wimg + IMG_OUT(0,t), bias + B_OUT(0,t),
                         (float*)(X + (size_t)OFFS_H[t]*C), 128, 0, 128, 1 };
            fill_chain(sgm, 1, t, 1);
        }
        gemm_fused<2><<<CTA_ALL, 256, SMEM_TOT>>>(SL);
    }

    // ---- layer 1: gather, then final outproj -> out (fp32) ----
    gather_nodes<<<(NN * 32 + 255)/256, 256>>>(KV, Q, p_rel + (size_t)NR*H, denom, agg);
    {
        SegList SL; SL.nSeg = 3;
        for (int t = 0; t < 3; t++) {
            Seg& sgm = SL.s[t];
            sgm.A = agg + (size_t)OFFS_H[t]*C;
            sgm.Xold = X + (size_t)OFFS_H[t]*C;
            sgm.denom = denom + (size_t)OFFS_H[t]*H;
            sgm.skip = skip + (size_t)(1*3 + t);
            sgm.ctaStart = starts[t]; sgm.M = NT_H[t];
            sgm.nTiles = 1;
            sgm.t[0] = { wimg + IMG_OUT(1,t), bias + B_OUT(1,t),
                         out + (size_t)OFFS_H[t]*C, 128, 0, 128, 0 };
        }
        gemm_fused<2><<<CTA_ALL, 256, SMEM_TOT>>>(SL);
    }
}